// round 1
// baseline (speedup 1.0000x reference)
#include <cuda_runtime.h>

#define NMAX 100000
#define HDIM 128

// ---------------- scratch (device globals; no cudaMalloc allowed) ----------------
__device__ float g_b0[(size_t)NMAX * HDIM];   // h0 (residual)
__device__ float g_b1[(size_t)NMAX * HDIM];   // t = h @ W (pre-aggregation)
__device__ float g_b2[(size_t)NMAX * HDIM];   // aggregation / h1 / h2
__device__ float g_dinv[NMAX];                // deg then rsqrt(deg)
__device__ float g_scale[HDIM];               // fused BN scale
__device__ float g_shift[HDIM];               // fused BN shift (incl. b_pre)

// ---------------- small prep kernels ----------------
__global__ void bn_coef_kernel(const float* __restrict__ b_pre,
                               const float* __restrict__ gamma,
                               const float* __restrict__ beta,
                               const float* __restrict__ mean,
                               const float* __restrict__ var) {
    int j = threadIdx.x;
    float s = gamma[j] * rsqrtf(var[j] + 1e-5f);
    g_scale[j] = s;
    g_shift[j] = (b_pre[j] - mean[j]) * s + beta[j];
}

__global__ void deg_init_kernel(float* __restrict__ deg, int n) {
    int i = blockIdx.x * 256 + threadIdx.x;
    if (i < n) deg[i] = 1.0f;   // self-loop weight
}

__global__ void deg_scatter_kernel(const int* __restrict__ dst,
                                   const float* __restrict__ ew,
                                   float* __restrict__ deg, int e) {
    int i = blockIdx.x * 256 + threadIdx.x;
    if (i < e) atomicAdd(&deg[dst[i]], ew[i]);
}

__global__ void deg_finish_kernel(float* __restrict__ deg, int n) {
    int i = blockIdx.x * 256 + threadIdx.x;
    if (i < n) deg[i] = rsqrtf(deg[i]);
}

// ---------------- 128-wide SGEMM: C[n,128] = A[n,128] @ W[128,128] ----------------
// epi==1: fused BN+ReLU epilogue using g_scale/g_shift
__global__ __launch_bounds__(256) void gemm128_kernel(
    const float* __restrict__ A, const float* __restrict__ W,
    float* __restrict__ C, int n, int epi)
{
    __shared__ float As[16][128];  // k-major (transposed)
    __shared__ float Ws[16][128];
    int tid = threadIdx.x;
    int row0 = blockIdx.x * 128;
    int tx = tid & 15, ty = tid >> 4;
    float acc[8][8];
    #pragma unroll
    for (int i = 0; i < 8; i++)
        #pragma unroll
        for (int j = 0; j < 8; j++) acc[i][j] = 0.0f;

    for (int kb = 0; kb < 128; kb += 16) {
        // A tile: 128 rows x 16 k, loaded as float4 along k, stored transposed
        #pragma unroll
        for (int l = 0; l < 2; l++) {
            int li = tid + l * 256;          // 0..511
            int r  = li >> 2;                // 0..127
            int k4 = li & 3;                 // 0..3
            int gr = row0 + r;
            float4 v = make_float4(0.f, 0.f, 0.f, 0.f);
            if (gr < n) v = *(const float4*)(A + (size_t)gr * 128 + kb + k4 * 4);
            As[k4 * 4 + 0][r] = v.x;
            As[k4 * 4 + 1][r] = v.y;
            As[k4 * 4 + 2][r] = v.z;
            As[k4 * 4 + 3][r] = v.w;
        }
        // W tile: rows kb..kb+15, all 128 cols
        #pragma unroll
        for (int l = 0; l < 2; l++) {
            int li = tid + l * 256;
            int kk = li >> 5;                // 0..15
            int j4 = li & 31;                // 0..31
            float4 v = *(const float4*)(W + (size_t)(kb + kk) * 128 + j4 * 4);
            *(float4*)&Ws[kk][j4 * 4] = v;
        }
        __syncthreads();
        #pragma unroll
        for (int kk = 0; kk < 16; kk++) {
            float a[8], b[8];
            *(float4*)&a[0] = *(const float4*)&As[kk][ty * 8];
            *(float4*)&a[4] = *(const float4*)&As[kk][ty * 8 + 4];
            *(float4*)&b[0] = *(const float4*)&Ws[kk][tx * 8];
            *(float4*)&b[4] = *(const float4*)&Ws[kk][tx * 8 + 4];
            #pragma unroll
            for (int i = 0; i < 8; i++)
                #pragma unroll
                for (int j = 0; j < 8; j++)
                    acc[i][j] = fmaf(a[i], b[j], acc[i][j]);
        }
        __syncthreads();
    }

    #pragma unroll
    for (int i = 0; i < 8; i++) {
        int gr = row0 + ty * 8 + i;
        if (gr >= n) break;
        #pragma unroll
        for (int j = 0; j < 8; j += 4) {
            int col = tx * 8 + j;
            float4 v = make_float4(acc[i][j], acc[i][j+1], acc[i][j+2], acc[i][j+3]);
            if (epi) {
                v.x = fmaxf(fmaf(v.x, g_scale[col+0], g_shift[col+0]), 0.f);
                v.y = fmaxf(fmaf(v.y, g_scale[col+1], g_shift[col+1]), 0.f);
                v.z = fmaxf(fmaf(v.z, g_scale[col+2], g_shift[col+2]), 0.f);
                v.w = fmaxf(fmaf(v.w, g_scale[col+3], g_shift[col+3]), 0.f);
            }
            *(float4*)(C + (size_t)gr * 128 + col) = v;
        }
    }
}

// ---------------- aggregation ----------------
// AGG[i] = T[i] * dinv[i]^2   (self-loop contribution as init)
__global__ void self_init_kernel(const float* __restrict__ T,
                                 const float* __restrict__ dinv,
                                 float* __restrict__ AGG, int n)
{
    size_t idx = (size_t)blockIdx.x * 256 + threadIdx.x;   // over n*32 float4s
    if (idx >= (size_t)n * 32) return;
    int row = (int)(idx >> 5);
    float c = dinv[row]; c *= c;
    float4 v = *(const float4*)(T + idx * 4);
    v.x *= c; v.y *= c; v.z *= c; v.w *= c;
    *(float4*)(AGG + idx * 4) = v;
}

// warp-per-edge scatter: AGG[dst] += T[src] * (dinv[src]*ew*dinv[dst])
__global__ __launch_bounds__(256) void edge_scatter_kernel(
    const int* __restrict__ src, const int* __restrict__ dst,
    const float* __restrict__ ew, const float* __restrict__ dinv,
    const float* __restrict__ T, float* __restrict__ AGG, int e)
{
    int eid = blockIdx.x * 8 + (threadIdx.x >> 5);
    if (eid >= e) return;
    int lane = threadIdx.x & 31;
    int s = src[eid], d = dst[eid];
    float c = dinv[s] * ew[eid] * dinv[d];
    float4 v = *(const float4*)(T + (size_t)s * 128 + lane * 4);
    float* p = AGG + (size_t)d * 128 + lane * 4;
    asm volatile("red.global.add.v4.f32 [%0], {%1,%2,%3,%4};"
                 :: "l"(p), "f"(v.x * c), "f"(v.y * c), "f"(v.z * c), "f"(v.w * c)
                 : "memory");
}

// X = relu(X + b[col])
__global__ void relu_bias_kernel(float* __restrict__ X, const float* __restrict__ b, int n) {
    size_t idx = (size_t)blockIdx.x * 256 + threadIdx.x;
    if (idx >= (size_t)n * 32) return;
    int col = ((int)idx & 31) * 4;
    float4 v = *(float4*)(X + idx * 4);
    v.x = fmaxf(v.x + b[col+0], 0.f);
    v.y = fmaxf(v.y + b[col+1], 0.f);
    v.z = fmaxf(v.z + b[col+2], 0.f);
    v.w = fmaxf(v.w + b[col+3], 0.f);
    *(float4*)(X + idx * 4) = v;
}

// X = X + b[col] + R  (conv2 bias + residual, no relu)
__global__ void bias_res_kernel(float* __restrict__ X, const float* __restrict__ b,
                                const float* __restrict__ R, int n) {
    size_t idx = (size_t)blockIdx.x * 256 + threadIdx.x;
    if (idx >= (size_t)n * 32) return;
    int col = ((int)idx & 31) * 4;
    float4 v = *(float4*)(X + idx * 4);
    float4 r = *(const float4*)(R + idx * 4);
    v.x += b[col+0] + r.x;
    v.y += b[col+1] + r.y;
    v.z += b[col+2] + r.z;
    v.w += b[col+3] + r.w;
    *(float4*)(X + idx * 4) = v;
}

// ---------------- classifier tail: LN(z+bc1) -> relu -> @Wc2 + bc2 ----------------
__global__ __launch_bounds__(256) void classifier_kernel(
    const float* __restrict__ Z, const float* __restrict__ bc1,
    const float* __restrict__ lng, const float* __restrict__ lnb,
    const float* __restrict__ Wc2, const float* __restrict__ bc2,
    float* __restrict__ out, int n)
{
    int row = blockIdx.x * 8 + (threadIdx.x >> 5);
    if (row >= n) return;
    int lane = threadIdx.x & 31;
    float4 z = *(const float4*)(Z + (size_t)row * 128 + lane * 4);
    float4 b = *(const float4*)(bc1 + lane * 4);
    z.x += b.x; z.y += b.y; z.z += b.z; z.w += b.w;
    float s = z.x + z.y + z.z + z.w;
    #pragma unroll
    for (int o = 16; o; o >>= 1) s += __shfl_xor_sync(0xffffffffu, s, o);
    float mu = s * (1.0f / 128.0f);
    float dx = z.x - mu, dy = z.y - mu, dz = z.z - mu, dw = z.w - mu;
    float v = dx*dx + dy*dy + dz*dz + dw*dw;
    #pragma unroll
    for (int o = 16; o; o >>= 1) v += __shfl_xor_sync(0xffffffffu, v, o);
    float rstd = rsqrtf(v * (1.0f / 128.0f) + 1e-5f);
    float4 g = *(const float4*)(lng + lane * 4);
    float4 bb = *(const float4*)(lnb + lane * 4);
    float q0 = fmaxf(fmaf(dx * rstd, g.x, bb.x), 0.f);
    float q1 = fmaxf(fmaf(dy * rstd, g.y, bb.y), 0.f);
    float q2 = fmaxf(fmaf(dz * rstd, g.z, bb.z), 0.f);
    float q3 = fmaxf(fmaf(dw * rstd, g.w, bb.w), 0.f);
    int base = lane * 4 * 3;     // Wc2 is [128,3] row-major
    float o0 = q0*Wc2[base+0] + q1*Wc2[base+3] + q2*Wc2[base+6] + q3*Wc2[base+9];
    float o1 = q0*Wc2[base+1] + q1*Wc2[base+4] + q2*Wc2[base+7] + q3*Wc2[base+10];
    float o2 = q0*Wc2[base+2] + q1*Wc2[base+5] + q2*Wc2[base+8] + q3*Wc2[base+11];
    #pragma unroll
    for (int o = 16; o; o >>= 1) {
        o0 += __shfl_xor_sync(0xffffffffu, o0, o);
        o1 += __shfl_xor_sync(0xffffffffu, o1, o);
        o2 += __shfl_xor_sync(0xffffffffu, o2, o);
    }
    if (lane == 0) {
        out[(size_t)row * 3 + 0] = o0 + bc2[0];
        out[(size_t)row * 3 + 1] = o1 + bc2[1];
        out[(size_t)row * 3 + 2] = o2 + bc2[2];
    }
}

// ---------------- launch ----------------
extern "C" void kernel_launch(void* const* d_in, const int* in_sizes, int n_in,
                              void* d_out, int out_size)
{
    const float* x     = (const float*)d_in[0];
    const int*   ei    = (const int*)  d_in[1];   // [2, E] int32
    const float* ea    = (const float*)d_in[2];
    const float* W_pre = (const float*)d_in[3];
    const float* b_pre = (const float*)d_in[4];
    const float* gam   = (const float*)d_in[5];
    const float* bet   = (const float*)d_in[6];
    const float* mean  = (const float*)d_in[7];
    const float* var   = (const float*)d_in[8];
    const float* W1    = (const float*)d_in[9];
    const float* b1v   = (const float*)d_in[10];
    const float* W2    = (const float*)d_in[11];
    const float* b2v   = (const float*)d_in[12];
    const float* Wc1   = (const float*)d_in[13];
    const float* bc1   = (const float*)d_in[14];
    const float* lng   = (const float*)d_in[15];
    const float* lnb   = (const float*)d_in[16];
    const float* Wc2   = (const float*)d_in[17];
    const float* bc2   = (const float*)d_in[18];
    float* out = (float*)d_out;

    int n = in_sizes[0] / 128;
    int e = in_sizes[2];
    const int* src = ei;
    const int* dst = ei + e;

    float *b0, *b1g, *b2g, *dinv;
    cudaGetSymbolAddress((void**)&b0,   g_b0);
    cudaGetSymbolAddress((void**)&b1g,  g_b1);
    cudaGetSymbolAddress((void**)&b2g,  g_b2);
    cudaGetSymbolAddress((void**)&dinv, g_dinv);

    int gb = (n + 127) / 128;                       // gemm blocks
    int eg = (e + 7) / 8;                           // edge scatter blocks (8 edges/block)
    int ng = (int)(((size_t)n * 32 + 255) / 256);   // elementwise blocks (float4 granularity)
    int nb = (n + 255) / 256;
    int eb = (e + 255) / 256;

    // degree / dinv (shared by both conv layers)
    bn_coef_kernel<<<1, 128>>>(b_pre, gam, bet, mean, var);
    deg_init_kernel<<<nb, 256>>>(dinv, n);
    deg_scatter_kernel<<<eb, 256>>>(dst, ea, dinv, e);
    deg_finish_kernel<<<nb, 256>>>(dinv, n);

    // h0 = relu(BN(x @ W_pre + b_pre))
    gemm128_kernel<<<gb, 256>>>(x, W_pre, b0, n, 1);

    // conv1: t = h0 @ W1 ; agg = norm-aggregate(t) ; h1 = relu(agg + b1)
    gemm128_kernel<<<gb, 256>>>(b0, W1, b1g, n, 0);
    self_init_kernel<<<ng, 256>>>(b1g, dinv, b2g, n);
    edge_scatter_kernel<<<eg, 256>>>(src, dst, ea, dinv, b1g, b2g, e);
    relu_bias_kernel<<<ng, 256>>>(b2g, b1v, n);

    // conv2: t = h1 @ W2 ; agg ; h2 = agg + b2 + h0
    gemm128_kernel<<<gb, 256>>>(b2g, W2, b1g, n, 0);
    self_init_kernel<<<ng, 256>>>(b1g, dinv, b2g, n);
    edge_scatter_kernel<<<eg, 256>>>(src, dst, ea, dinv, b1g, b2g, e);
    bias_res_kernel<<<ng, 256>>>(b2g, b2v, b0, n);

    // classifier: z = h2 @ Wc1 ; out = relu(LN(z + bc1)) @ Wc2 + bc2
    gemm128_kernel<<<gb, 256>>>(b2g, Wc1, b1g, n, 0);
    classifier_kernel<<<(n + 7) / 8, 256>>>(b1g, bc1, lng, lnb, Wc2, bc2, out, n);
}